// round 14
// baseline (speedup 1.0000x reference)
#include <cuda_runtime.h>
#include <cuda_bf16.h>

// Welford running mean/variance over batch dim of x: (B, C, H, W), B=256, CHW=262144.
// One scalar thread per spatial position (262,144 threads).
//
// R14 = R13 (dual half-batch Welford streams, shared-memory reciprocal tables,
//       exact Chan merge; regs=32, occ 81%) with the loop unrolled by 2 and the
//       FOUR loads (vA0, vB0, vA1, vB1) front-batched before any store/compute.
//       Goal: true MLP~4 per warp inside the default register budget — the lean
//       loop body (no MUFU, no counters) is what R12 lacked.
//
// Output layout (float32, concatenated):
//   [0, B*CHW) : x passthrough | [+0,+CHW): m | [+CHW,+2CHW): s
//   [+2CHW,+3CHW): neuron_nonzero | [last]: n_samples + B

__global__ void __launch_bounds__(256) welford_dual_u2(
    const float* __restrict__ x,
    const float* __restrict__ m_in,
    const float* __restrict__ s_in,
    const int*   __restrict__ nn_in,
    const int*   __restrict__ n_in,
    float*       __restrict__ out,
    int B, int CHW)
{
    __shared__ float invA_tab[128];
    __shared__ float invB_tab[128];

    const int H  = B >> 1;                 // 128
    const int n0 = n_in[0];

    // Thread-invariant reciprocal tables (same math as the reference recurrence).
    {
        int t = threadIdx.x;
        if (t < H) {
            invA_tab[t] = __fdividef(1.0f, (float)(n0 + t + 1));
            invB_tab[t] = __fdividef(1.0f, (float)(t + 1));
        }
    }
    __syncthreads();

    int p = blockIdx.x * blockDim.x + threadIdx.x;
    if (p >= CHW) return;

    const size_t step = (size_t)CHW;

    // Stream A continues the input state over b in [0, H);
    // Stream B runs standalone from zero over b in [H, B).
    float mA = m_in[p], sA = s_in[p];
    float mB = 0.0f,    sB = 0.0f;
    int   nnA = nn_in[p], nnB = 0;

    const float* xA = x + p;
    const float* xB = x + p + (size_t)H * step;
    float*       oA = out + p;
    float*       oB = out + p + (size_t)H * step;

    #pragma unroll 2
    for (int b = 0; b < H; b += 2) {
        size_t off0 = (size_t)b * step;
        size_t off1 = off0 + step;

        // Phase 1: FOUR independent loads, all issued before any dependent op.
        float va0 = xA[off0];
        float vb0 = xB[off0];
        float va1 = xA[off1];
        float vb1 = xB[off1];

        // Phase 2: passthrough stores.
        oA[off0] = va0;
        oB[off0] = vb0;
        oA[off1] = va1;
        oB[off1] = vb1;

        // Phase 3: Welford updates (table reciprocals; exact reference order
        // within each stream).
        float iA0 = invA_tab[b];
        float iB0 = invB_tab[b];
        float iA1 = invA_tab[b + 1];
        float iB1 = invB_tab[b + 1];

        nnA += (va0 != 0.0f);
        nnB += (vb0 != 0.0f);
        nnA += (va1 != 0.0f);
        nnB += (vb1 != 0.0f);

        float om;
        om = mA; mA += (va0 - mA) * iA0; sA += (va0 - mA) * (va0 - om);
        om = mB; mB += (vb0 - mB) * iB0; sB += (vb0 - mB) * (vb0 - om);
        om = mA; mA += (va1 - mA) * iA1; sA += (va1 - mA) * (va1 - om);
        om = mB; mB += (vb1 - mB) * iB1; sB += (vb1 - mB) * (vb1 - om);
    }

    // Exact Chan merge: A carries n0+H samples, B carries H samples.
    float nAf = (float)(n0 + H);
    float nBf = (float)H;
    float nTf = nAf + nBf;
    float invT = __fdividef(1.0f, nTf);
    float d  = mB - mA;
    float m  = mA + d * (nBf * invT);
    float s  = sA + sB + d * d * (nAf * nBf * invT);
    int   nn = nnA + nnB;

    size_t base = (size_t)B * step;
    out[base + p]            = m;
    out[base + step + p]     = s;
    out[base + 2 * step + p] = (float)nn;
    if (p == 0) {
        out[base + 3 * step] = (float)(n0 + B);
    }
}

extern "C" void kernel_launch(void* const* d_in, const int* in_sizes, int n_in,
                              void* d_out, int out_size)
{
    const float* x  = (const float*)d_in[0];
    const float* m  = (const float*)d_in[1];
    const float* s  = (const float*)d_in[2];
    const int*   nn = (const int*)d_in[3];
    const int*   n  = (const int*)d_in[4];
    float* out = (float*)d_out;

    const int CHW = in_sizes[1];          // 262144
    const int B   = in_sizes[0] / CHW;    // 256

    const int threads = 256;
    const int blocks = (CHW + threads - 1) / threads;  // 1024
    welford_dual_u2<<<blocks, threads>>>(x, m, s, nn, n, out, B, CHW);
}